// round 14
// baseline (speedup 1.0000x reference)
#include <cuda_runtime.h>
#include <cuda_bf16.h>
#include <cuda_fp16.h>
#include <cstdint>

#define SEQ 4096
#define DM  1024
#define NH  16
#define DH  64
#define WIN 256

// ---------------------------------------------------------------------------
// Scratch (allocation-free rule)
// ---------------------------------------------------------------------------
__device__ __half    g_qh[SEQ * DM];          // q (pre-scaled 0.125*log2e), fp16
__device__ __half    g_kh[SEQ * DM];          // k, fp16
__device__ unsigned  g_vp[(SEQ / 2) * DM];    // v, fp16 k-pair-packed
__device__ __half    g_xh[SEQ * DM];          // x as fp16
__device__ __half    g_ao[SEQ * DM];          // attention output as fp16
__device__ __half    g_wt[4][DM * DM];        // W^T as fp16 (q,k,v,o)

// ---------------------------------------------------------------------------
// Helpers
// ---------------------------------------------------------------------------
__device__ __forceinline__ uint32_t smem_u32(const void* p) {
    uint32_t a;
    asm("{ .reg .u64 t; cvta.to.shared.u64 t, %1; cvt.u32.u64 %0, t; }" : "=r"(a) : "l"(p));
    return a;
}
__device__ __forceinline__ float ex2(float x) {
    float r; asm("ex2.approx.ftz.f32 %0, %1;" : "=f"(r) : "f"(x)); return r;
}
// fp16 MMA m16n8k16, fp32 accum
__device__ __forceinline__ void mma_fp(float* c, const unsigned* a, const unsigned* b) {
    asm volatile("mma.sync.aligned.m16n8k16.row.col.f32.f16.f16.f32 "
        "{%0,%1,%2,%3},{%4,%5,%6,%7},{%8,%9},{%0,%1,%2,%3};"
        : "+f"(c[0]), "+f"(c[1]), "+f"(c[2]), "+f"(c[3])
        : "r"(a[0]), "r"(a[1]), "r"(a[2]), "r"(a[3]), "r"(b[0]), "r"(b[1]));
}
#define CP16(dst, src) \
    asm volatile("cp.async.cg.shared.global [%0], [%1], 16;" :: "r"(dst), "l"(src))
#define CP_COMMIT() asm volatile("cp.async.commit_group;" ::: "memory")
#define CP_WAIT1()  asm volatile("cp.async.wait_group 1;" ::: "memory")
#define LDSM4(r0, r1, r2, r3, a) \
    asm volatile("ldmatrix.sync.aligned.m8n8.x4.shared.b16 {%0,%1,%2,%3}, [%4];" \
        : "=r"(r0), "=r"(r1), "=r"(r2), "=r"(r3) : "r"(a))

// q scale: 0.125 (1/sqrt(64)) * log2(e), folded so softmax can use exp2
#define QSCALE 0.180336880f

// ---------------------------------------------------------------------------
// Conversion kernels (one-time per launch)
// ---------------------------------------------------------------------------
__global__ void tohalf(const float* __restrict__ src, __half* __restrict__ dst) {
    int i = (blockIdx.x * blockDim.x + threadIdx.x) * 4;
    float4 v = *(const float4*)(src + i);
    __half2 a = __floats2half2_rn(v.x, v.y);
    __half2 b = __floats2half2_rn(v.z, v.w);
    *(uint2*)(dst + i) = make_uint2(*(unsigned*)&a, *(unsigned*)&b);
}

// All four W [K=DM][N=DM] -> W^T [N][K] fp16, one launch (grid.z = 4)
__global__ void tsplit4h(const float* __restrict__ W0, const float* __restrict__ W1,
                         const float* __restrict__ W2, const float* __restrict__ W3,
                         __half* __restrict__ T) {
    __shared__ float tile[32][33];
    const int z = blockIdx.z;
    const float* W = z == 0 ? W0 : (z == 1 ? W1 : (z == 2 ? W2 : W3));
    __half* t_out = T + (size_t)z * DM * DM;
    int k0 = blockIdx.y * 32, n0 = blockIdx.x * 32;
    int tx = threadIdx.x, ty = threadIdx.y;
#pragma unroll
    for (int j = 0; j < 32; j += 8)
        tile[ty + j][tx] = W[(size_t)(k0 + ty + j) * DM + n0 + tx];
    __syncthreads();
#pragma unroll
    for (int j = 0; j < 32; j += 8)
        t_out[(size_t)(n0 + ty + j) * DM + k0 + tx] = __float2half(tile[tx][ty + j]);
}

// ---------------------------------------------------------------------------
// Pipelined 1-pass fp16 HMMA GEMM. 256 thr (8 warps 2x4), tile 128x128,
// BK=32 (2 k-steps per barrier -> 32 syncs instead of 64, 2x ILP between
// barriers). 3-slot / 2-deep cp.async ring, single __syncthreads per iter
// (refill targets slot (t+2)%3, readers finished at iter t-1).
// Smem rows: 64B data @ 80B pitch (LDSM reads conflict-free: banks 20r+4q).
// FUSED epilogue writes q/k/v attention scratch; else fp32 out.
// m_base selects the row-half (multi-stream split).
// ---------------------------------------------------------------------------
#define ROWB    80
#define PLANEB  (128 * ROWB)        // 10240
#define STAGEB  (2 * PLANEB)        // 20480
#define NSTAGE  3
#define GSMEM   (NSTAGE * STAGEB)   // 61440

template <bool FUSED>
__global__ void __launch_bounds__(256, 2) gemm_fp16(
    const __half* __restrict__ A, const __half* __restrict__ BT,
    float* __restrict__ out, int m_base)
{
    extern __shared__ char dynsmem[];
    const uint32_t sb = smem_u32(dynsmem);
    const int tid = threadIdx.x, lane = tid & 31, warp = tid >> 5;
    const int m0 = m_base + blockIdx.y * 128;
    const int nb = blockIdx.x;
    const int nbase = nb * 128;
    const int col0 = (nb & 7) * 128;

    // cp.async task: 4 chunks of 16B per thread per stage (2 per plane).
    // chunk -> (row r, quarter q): sdst = r*80 + q*16, gsrc col = q*8 halves.
    const int r0 = tid >> 2, q0 = tid & 3;
    const __half* gsrcA = A  + (size_t)(m0 + r0) * DM + q0 * 8;
    const __half* gsrcB = BT + (size_t)(nbase + r0) * DM + q0 * 8;
    const uint32_t sdst = r0 * ROWB + q0 * 16;
    const uint32_t sdst2 = sdst + 64 * ROWB;          // rows r0+64
    const size_t   goff2 = (size_t)64 * DM;

    const int wm = (warp >> 2) * 64, wn = (warp & 3) * 32;
    const int lrow = lane & 15, lcol = lane & 16;
    const uint32_t abase = (wm + lrow) * ROWB + lcol;   // + mt*16*ROWB + ks*32
    const uint32_t bbase = (wn + lrow) * ROWB + lcol;   // + j*16*ROWB + ks*32

    float acc[4][4][4];
#pragma unroll
    for (int a = 0; a < 4; a++)
#pragma unroll
        for (int b = 0; b < 4; b++)
#pragma unroll
            for (int c = 0; c < 4; c++) acc[a][b][c] = 0.0f;

    // Prologue: tiles 0..1 into slots 0..1 (2-deep)
#pragma unroll
    for (int t = 0; t < 2; t++) {
        const uint32_t st = sb + t * STAGEB;
        const int kc = t * 32;
        CP16(st + sdst,           gsrcA + kc);
        CP16(st + sdst2,          gsrcA + goff2 + kc);
        CP16(st + PLANEB + sdst,  gsrcB + kc);
        CP16(st + PLANEB + sdst2, gsrcB + goff2 + kc);
        CP_COMMIT();
    }

    const int KT = DM / 32;  // 32
    for (int t = 0; t < KT; t++) {
        CP_WAIT1();
        __syncthreads();
        const uint32_t st = sb + (t % NSTAGE) * STAGEB;

        // Refill tile t+2 into slot (t+2)%3 (readers done at iter t-1)
        if (t + 2 < KT) {
            const uint32_t st2 = sb + ((t + 2) % NSTAGE) * STAGEB;
            const int kc = (t + 2) * 32;
            CP16(st2 + sdst,           gsrcA + kc);
            CP16(st2 + sdst2,          gsrcA + goff2 + kc);
            CP16(st2 + PLANEB + sdst,  gsrcB + kc);
            CP16(st2 + PLANEB + sdst2, gsrcB + goff2 + kc);
        }
        CP_COMMIT();

#pragma unroll
        for (int ks = 0; ks < 2; ks++) {
            unsigned bf[4][2];
#pragma unroll
            for (int j = 0; j < 2; j++) {
                unsigned b0, b1, b2, b3;
                LDSM4(b0, b1, b2, b3,
                      st + PLANEB + bbase + ks * 32 + j * (16 * ROWB));
                bf[2 * j][0] = b0; bf[2 * j + 1][0] = b1;
                bf[2 * j][1] = b2; bf[2 * j + 1][1] = b3;
            }
#pragma unroll
            for (int mt = 0; mt < 4; mt++) {
                unsigned af[4];
                LDSM4(af[0], af[1], af[2], af[3],
                      st + abase + ks * 32 + mt * (16 * ROWB));
#pragma unroll
                for (int nt = 0; nt < 4; nt++)
                    mma_fp(acc[mt][nt], af, bf[nt]);
            }
        }
    }

    const int g = lane >> 2, tig = lane & 3;
    if (!FUSED) {
#pragma unroll
        for (int mt = 0; mt < 4; mt++)
#pragma unroll
            for (int nt = 0; nt < 4; nt++) {
                int row = m0 + wm + mt * 16 + g;
                int cc = col0 + wn + nt * 8 + 2 * tig;
                *(float2*)(out + (size_t)row * DM + cc) =
                    make_float2(acc[mt][nt][0], acc[mt][nt][1]);
                *(float2*)(out + (size_t)(row + 8) * DM + cc) =
                    make_float2(acc[mt][nt][2], acc[mt][nt][3]);
            }
    } else {
        const int grp = nb >> 3;   // 0=q, 1=k, 2=v (uniform per block)
#pragma unroll
        for (int mt = 0; mt < 4; mt++)
#pragma unroll
            for (int nt = 0; nt < 4; nt++) {
                int row = m0 + wm + mt * 16 + g;
                int cc = col0 + wn + nt * 8 + 2 * tig;
                if (grp == 0) {
                    __half2 h0 = __floats2half2_rn(acc[mt][nt][0] * QSCALE,
                                                   acc[mt][nt][1] * QSCALE);
                    __half2 h1 = __floats2half2_rn(acc[mt][nt][2] * QSCALE,
                                                   acc[mt][nt][3] * QSCALE);
                    *(unsigned*)(g_qh + (size_t)row * DM + cc) = *(unsigned*)&h0;
                    *(unsigned*)(g_qh + (size_t)(row + 8) * DM + cc) = *(unsigned*)&h1;
                } else if (grp == 1) {
                    __half2 h0 = __floats2half2_rn(acc[mt][nt][0], acc[mt][nt][1]);
                    __half2 h1 = __floats2half2_rn(acc[mt][nt][2], acc[mt][nt][3]);
                    *(unsigned*)(g_kh + (size_t)row * DM + cc) = *(unsigned*)&h0;
                    *(unsigned*)(g_kh + (size_t)(row + 8) * DM + cc) = *(unsigned*)&h1;
                } else {
                    float a0 = acc[mt][nt][0], a1 = acc[mt][nt][1];
                    float a2 = acc[mt][nt][2], a3 = acc[mt][nt][3];
                    float b0 = __shfl_down_sync(0xffffffffu, a0, 4);
                    float b1 = __shfl_down_sync(0xffffffffu, a1, 4);
                    float b2 = __shfl_down_sync(0xffffffffu, a2, 4);
                    float b3 = __shfl_down_sync(0xffffffffu, a3, 4);
                    if (!(g & 1)) {
                        int prow = row >> 1;
                        __half2 p0 = __floats2half2_rn(a0, b0);
                        __half2 p1 = __floats2half2_rn(a1, b1);
                        *(uint2*)(g_vp + (size_t)prow * DM + cc) =
                            make_uint2(*(unsigned*)&p0, *(unsigned*)&p1);
                        __half2 p2 = __floats2half2_rn(a2, b2);
                        __half2 p3 = __floats2half2_rn(a3, b3);
                        *(uint2*)(g_vp + (size_t)(prow + 4) * DM + cc) =
                            make_uint2(*(unsigned*)&p2, *(unsigned*)&p3);
                    }
                }
            }
    }
}

// ---------------------------------------------------------------------------
// Warp-tiled flash attention (unchanged from the 196.5us run).
// ---------------------------------------------------------------------------
__global__ void __launch_bounds__(128, 4) attn_kernel(int qblk_off)
{
    __shared__ unsigned Qh[64][36];
    __shared__ unsigned Kh[64][36];
    __shared__ unsigned Vs[32][72];
    __shared__ unsigned Ps[64][36];

    const int h = blockIdx.y, t0 = (blockIdx.x + qblk_off) * 64;
    const int tid = threadIdx.x;
    const int lane = tid & 31, warp = tid >> 5;
    const int g = lane >> 2, tig = lane & 3;
    const int wq = t0 + warp * 16;
    const int rA = warp * 16 + g;

#pragma unroll
    for (int u = 0; u < 4; u++) {
        int idx = tid + u * 128;
        int r = idx >> 3, c = idx & 7;
        *(uint4*)&Qh[r][c * 4] =
            *(const uint4*)(g_qh + (size_t)(t0 + r) * DM + h * DH + c * 8);
    }

    float o[8][4];
#pragma unroll
    for (int nt = 0; nt < 8; nt++)
#pragma unroll
        for (int e = 0; e < 4; e++) o[nt][e] = 0.0f;
    float m0 = -1e30f, m1 = -1e30f, l0 = 0.0f, l1 = 0.0f;

    const int jlo = max(0, t0 - WIN);

    for (int jc = t0; jc >= jlo; jc -= 64) {
        __syncthreads();
#pragma unroll
        for (int u = 0; u < 4; u++) {
            int idx = tid + u * 128;
            int r = idx >> 3, c = idx & 7;
            *(uint4*)&Kh[r][c * 4] =
                *(const uint4*)(g_kh + (size_t)(jc + r) * DM + h * DH + c * 8);
        }
#pragma unroll
        for (int u = 0; u < 4; u++) {
            int idx = tid + u * 128;
            int r = idx >> 4, c = idx & 15;
            *(uint4*)&Vs[r][c * 4] =
                *(const uint4*)(g_vp + (size_t)((jc >> 1) + r) * DM + h * DH + c * 4);
        }
        __syncthreads();

        const bool is_first = (jc == t0);
        const bool is_last  = (jc == t0 - WIN);
        const int nt0 = is_last ? 2 * warp : 0;
        const int ks0 = is_last ? warp : 0;

        float s[8][4];
#pragma unroll
        for (int nt = 0; nt < 8; nt++)
#pragma unroll
            for (int e = 0; e < 4; e++) s[nt][e] = 0.0f;
#pragma unroll
        for (int ks = 0; ks < 4; ks++) {
            unsigned qf[4];
            qf[0] = Qh[rA][ks * 8 + tig];     qf[1] = Qh[rA + 8][ks * 8 + tig];
            qf[2] = Qh[rA][ks * 8 + tig + 4]; qf[3] = Qh[rA + 8][ks * 8 + tig + 4];
#pragma unroll
            for (int nt = 0; nt < 8; nt++) {
                if (nt >= nt0) {
                    unsigned bf[2];
                    bf[0] = Kh[nt * 8 + g][ks * 8 + tig];
                    bf[1] = Kh[nt * 8 + g][ks * 8 + tig + 4];
                    mma_fp(s[nt], qf, bf);
                }
            }
        }

        const int r0 = wq + g, r1 = r0 + 8;
        if (is_first || is_last) {
#pragma unroll
            for (int nt = 0; nt < 8; nt++) {
#pragma unroll
                for (int e = 0; e < 2; e++) {
                    int j = jc + nt * 8 + 2 * tig + e;
                    if (j > r0 || j + WIN < r0) s[nt][e] = -1e30f;
                    if (j > r1 || j + WIN < r1) s[nt][2 + e] = -1e30f;
                }
            }
        }

        float mx0 = -1e30f, mx1 = -1e30f;
#pragma unroll
        for (int nt = 0; nt < 8; nt++) {
            mx0 = fmaxf(mx0, fmaxf(s[nt][0], s[nt][1]));
            mx1 = fmaxf(mx1, fmaxf(s[nt][2], s[nt][3]));
        }
        mx0 = fmaxf(mx0, __shfl_xor_sync(0xffffffffu, mx0, 1));
        mx0 = fmaxf(mx0, __shfl_xor_sync(0xffffffffu, mx0, 2));
        mx1 = fmaxf(mx1, __shfl_xor_sync(0xffffffffu, mx1, 1));
        mx1 = fmaxf(mx1, __shfl_xor_sync(0xffffffffu, mx1, 2));
        float mn0 = fmaxf(m0, mx0), mn1 = fmaxf(m1, mx1);
        float c0 = ex2(m0 - mn0), c1 = ex2(m1 - mn1);
        m0 = mn0; m1 = mn1;
        l0 *= c0; l1 *= c1;
#pragma unroll
        for (int nt = 0; nt < 8; nt++) {
            o[nt][0] *= c0; o[nt][1] *= c0;
            o[nt][2] *= c1; o[nt][3] *= c1;
        }
        float ls0 = 0.0f, ls1 = 0.0f;
#pragma unroll
        for (int nt = 0; nt < 8; nt++) {
            float p00 = ex2(s[nt][0] - mn0), p01 = ex2(s[nt][1] - mn0);
            float p10 = ex2(s[nt][2] - mn1), p11 = ex2(s[nt][3] - mn1);
            ls0 += p00 + p01; ls1 += p10 + p11;
            __half2 w0 = __floats2half2_rn(p00, p01);
            __half2 w1 = __floats2half2_rn(p10, p11);
            Ps[rA][nt * 4 + tig] = *(unsigned*)&w0;
            Ps[rA + 8][nt * 4 + tig] = *(unsigned*)&w1;
        }
        ls0 += __shfl_xor_sync(0xffffffffu, ls0, 1);
        ls0 += __shfl_xor_sync(0xffffffffu, ls0, 2);
        ls1 += __shfl_xor_sync(0xffffffffu, ls1, 1);
        ls1 += __shfl_xor_sync(0xffffffffu, ls1, 2);
        l0 += ls0; l1 += ls1;
        __syncwarp();

#pragma unroll
        for (int ks2 = 0; ks2 < 4; ks2++) {
            if (ks2 >= ks0) {
                unsigned pa[4];
                pa[0] = Ps[rA][ks2 * 8 + tig];
                pa[1] = Ps[rA + 8][ks2 * 8 + tig];
                pa[2] = Ps[rA][ks2 * 8 + tig + 4];
                pa[3] = Ps[rA + 8][ks2 * 8 + tig + 4];
#pragma unroll
                for (int nt = 0; nt < 8; nt++) {
                    unsigned vb[2];
                    vb[0] = Vs[ks2 * 8 + tig][nt * 8 + g];
                    vb[1] = Vs[ks2 * 8 + tig + 4][nt * 8 + g];
                    mma_fp(o[nt], pa, vb);
                }
            }
        }
    }

    const float inv0 = 1.0f / l0, inv1 = 1.0f / l1;
#pragma unroll
    for (int nt = 0; nt < 8; nt++) {
        int col = h * DH + nt * 8 + 2 * tig;
        __half2 a = __floats2half2_rn(o[nt][0] * inv0, o[nt][1] * inv0);
        __half2 b = __floats2half2_rn(o[nt][2] * inv1, o[nt][3] * inv1);
        *(unsigned*)(g_ao + (size_t)(wq + g) * DM + col) = *(unsigned*)&a;
        *(unsigned*)(g_ao + (size_t)(wq + g + 8) * DM + col) = *(unsigned*)&b;
    }
}

// ---------------------------------------------------------------------------
// Launch: EXACT R12 schedule (the 196.5us winner).
//   legacy: conv -> QKV-A -> attnA -> O-A -> (join) -> O-B
//   s2 (low prio): QKV-B -> attnB
// ---------------------------------------------------------------------------
extern "C" void kernel_launch(void* const* d_in, const int* in_sizes, int n_in,
                              void* d_out, int out_size)
{
    const float* x  = (const float*)d_in[0];
    const float* Wq = (const float*)d_in[1];
    const float* Wk = (const float*)d_in[2];
    const float* Wv = (const float*)d_in[3];
    const float* Wo = (const float*)d_in[4];
    float* out = (float*)d_out;

    __half *xh, *ao, *wt;
    cudaGetSymbolAddress((void**)&xh, g_xh);
    cudaGetSymbolAddress((void**)&ao, g_ao);
    cudaGetSymbolAddress((void**)&wt, g_wt);

    cudaFuncSetAttribute(gemm_fp16<true>,  cudaFuncAttributeMaxDynamicSharedMemorySize, GSMEM);
    cudaFuncSetAttribute(gemm_fp16<false>, cudaFuncAttributeMaxDynamicSharedMemorySize, GSMEM);

    int prLo = 0, prHi = 0;
    cudaDeviceGetStreamPriorityRange(&prLo, &prHi);   // prLo = least urgent
    cudaStream_t s2;
    cudaStreamCreateWithPriority(&s2, cudaStreamNonBlocking, prLo);
    cudaEvent_t evConv, evA, evB;
    cudaEventCreateWithFlags(&evConv, cudaEventDisableTiming);
    cudaEventCreateWithFlags(&evA,    cudaEventDisableTiming);
    cudaEventCreateWithFlags(&evB,    cudaEventDisableTiming);

    // One-time conversions (legacy stream)
    tsplit4h<<<dim3(DM / 32, DM / 32, 4), dim3(32, 8)>>>(Wq, Wk, Wv, Wo, wt);
    tohalf<<<SEQ * DM / 1024, 256>>>(x, xh);
    cudaEventRecord(evConv, 0);
    cudaStreamWaitEvent(s2, evConv, 0);

    // QKV GEMM, row-halved: A on legacy (high prio), B on s2 (low prio)
    gemm_fp16<true><<<dim3(24, SEQ / 256), 256, GSMEM, 0>>>(xh, wt, nullptr, 0);
    gemm_fp16<true><<<dim3(24, SEQ / 256), 256, GSMEM, s2>>>(xh, wt, nullptr, SEQ / 2);
    cudaEventRecord(evA, 0);

    // Attention halves
    attn_kernel<<<dim3(32, NH), 128, 0, 0>>>(0);          // rows 0..2047 only
    cudaStreamWaitEvent(s2, evA, 0);
    attn_kernel<<<dim3(32, NH), 128, 0, s2>>>(32);        // needs both halves

    // O-projection halves
    gemm_fp16<false><<<dim3(8, SEQ / 256), 256, GSMEM, 0>>>(
        ao, wt + 3 * (size_t)DM * DM, out, 0);
    cudaEventRecord(evB, s2);
    cudaStreamWaitEvent(0, evB, 0);                        // join fork
    gemm_fp16<false><<<dim3(8, SEQ / 256), 256, GSMEM, 0>>>(
        ao, wt + 3 * (size_t)DM * DM, out, SEQ / 2);
}

// round 15
// speedup vs baseline: 1.1282x; 1.1282x over previous
#include <cuda_runtime.h>
#include <cuda_bf16.h>
#include <cuda_fp16.h>
#include <cstdint>

#define SEQ 4096
#define DM  1024
#define NH  16
#define DH  64
#define WIN 256

// ---------------------------------------------------------------------------
// Scratch (allocation-free rule)
// ---------------------------------------------------------------------------
__device__ __half    g_qh[SEQ * DM];          // q (pre-scaled 0.125*log2e), fp16
__device__ __half    g_kh[SEQ * DM];          // k, fp16
__device__ unsigned  g_vp[(SEQ / 2) * DM];    // v, fp16 k-pair-packed
__device__ __half    g_xh[SEQ * DM];          // x as fp16
__device__ __half    g_ao[SEQ * DM];          // attention output as fp16
__device__ __half    g_wt[4][DM * DM];        // W^T as fp16 (q,k,v,o)

// ---------------------------------------------------------------------------
// Helpers
// ---------------------------------------------------------------------------
__device__ __forceinline__ uint32_t smem_u32(const void* p) {
    uint32_t a;
    asm("{ .reg .u64 t; cvta.to.shared.u64 t, %1; cvt.u32.u64 %0, t; }" : "=r"(a) : "l"(p));
    return a;
}
__device__ __forceinline__ float ex2(float x) {
    float r; asm("ex2.approx.ftz.f32 %0, %1;" : "=f"(r) : "f"(x)); return r;
}
// fp16 MMA m16n8k16, fp32 accum
__device__ __forceinline__ void mma_fp(float* c, const unsigned* a, const unsigned* b) {
    asm volatile("mma.sync.aligned.m16n8k16.row.col.f32.f16.f16.f32 "
        "{%0,%1,%2,%3},{%4,%5,%6,%7},{%8,%9},{%0,%1,%2,%3};"
        : "+f"(c[0]), "+f"(c[1]), "+f"(c[2]), "+f"(c[3])
        : "r"(a[0]), "r"(a[1]), "r"(a[2]), "r"(a[3]), "r"(b[0]), "r"(b[1]));
}
#define CP16(dst, src) \
    asm volatile("cp.async.cg.shared.global [%0], [%1], 16;" :: "r"(dst), "l"(src))
#define CP_COMMIT() asm volatile("cp.async.commit_group;" ::: "memory")
#define CP_WAIT2()  asm volatile("cp.async.wait_group 2;" ::: "memory")
#define LDSM4(r0, r1, r2, r3, a) \
    asm volatile("ldmatrix.sync.aligned.m8n8.x4.shared.b16 {%0,%1,%2,%3}, [%4];" \
        : "=r"(r0), "=r"(r1), "=r"(r2), "=r"(r3) : "r"(a))

// q scale: 0.125 (1/sqrt(64)) * log2(e), folded so softmax can use exp2
#define QSCALE 0.180336880f

// ---------------------------------------------------------------------------
// Conversion kernels (one-time per launch)
// ---------------------------------------------------------------------------
__global__ void tohalf(const float* __restrict__ src, __half* __restrict__ dst) {
    int i = (blockIdx.x * blockDim.x + threadIdx.x) * 4;
    float4 v = *(const float4*)(src + i);
    __half2 a = __floats2half2_rn(v.x, v.y);
    __half2 b = __floats2half2_rn(v.z, v.w);
    *(uint2*)(dst + i) = make_uint2(*(unsigned*)&a, *(unsigned*)&b);
}

// All four W [K=DM][N=DM] -> W^T [N][K] fp16, one launch (grid.z = 4)
__global__ void tsplit4h(const float* __restrict__ W0, const float* __restrict__ W1,
                         const float* __restrict__ W2, const float* __restrict__ W3,
                         __half* __restrict__ T) {
    __shared__ float tile[32][33];
    const int z = blockIdx.z;
    const float* W = z == 0 ? W0 : (z == 1 ? W1 : (z == 2 ? W2 : W3));
    __half* t_out = T + (size_t)z * DM * DM;
    int k0 = blockIdx.y * 32, n0 = blockIdx.x * 32;
    int tx = threadIdx.x, ty = threadIdx.y;
#pragma unroll
    for (int j = 0; j < 32; j += 8)
        tile[ty + j][tx] = W[(size_t)(k0 + ty + j) * DM + n0 + tx];
    __syncthreads();
#pragma unroll
    for (int j = 0; j < 32; j += 8)
        t_out[(size_t)(n0 + ty + j) * DM + k0 + tx] = __float2half(tile[tx][ty + j]);
}

// ---------------------------------------------------------------------------
// Pipelined 1-pass fp16 HMMA GEMM — EXACT R12 device code (the 63.3us/half
// version): 256 thr (8 warps 2x4), tile 128x128, BK=16, 4-slot / 3-deep
// cp.async ring (3 tiles outstanding), single __syncthreads per iteration.
// FUSED epilogue writes q/k/v attention scratch; else fp32 out.
// ---------------------------------------------------------------------------
#define ROWB    48
#define PLANEB  (128 * ROWB)        // 6144
#define STAGEB  (2 * PLANEB)        // 12288
#define NSTAGE  4
#define GSMEM   (NSTAGE * STAGEB)   // 49152

template <bool FUSED>
__global__ void __launch_bounds__(256, 2) gemm_fp16(
    const __half* __restrict__ A, const __half* __restrict__ BT,
    float* __restrict__ out, int m_base)
{
    extern __shared__ char dynsmem[];
    const uint32_t sb = smem_u32(dynsmem);
    const int tid = threadIdx.x, lane = tid & 31, warp = tid >> 5;
    const int m0 = m_base + blockIdx.y * 128;
    const int nb = blockIdx.x;
    const int nbase = nb * 128;
    const int col0 = (nb & 7) * 128;

    const int r = tid >> 1, hf = tid & 1;
    const __half* gsrcA = A  + (size_t)(m0 + r) * DM + hf * 8;
    const __half* gsrcB = BT + (size_t)(nbase + r) * DM + hf * 8;
    const uint32_t sdst = r * ROWB + hf * 16;

    const int wm = (warp >> 2) * 64, wn = (warp & 3) * 32;
    const int lrow = lane & 15, lcol = lane & 16;
    const uint32_t abase = (wm + lrow) * ROWB + lcol;
    const uint32_t bbase = (wn + lrow) * ROWB + lcol;

    float acc[4][4][4];
#pragma unroll
    for (int a = 0; a < 4; a++)
#pragma unroll
        for (int b = 0; b < 4; b++)
#pragma unroll
            for (int c = 0; c < 4; c++) acc[a][b][c] = 0.0f;

    // Prologue: tiles 0..2 into slots 0..2 (3-deep)
#pragma unroll
    for (int t = 0; t < 3; t++) {
        const uint32_t st = sb + t * STAGEB;
        const int kc = t * 16;
        CP16(st + sdst,          gsrcA + kc);
        CP16(st + PLANEB + sdst, gsrcB + kc);
        CP_COMMIT();
    }

    const int KT = DM / 16;  // 64
    for (int t = 0; t < KT; t++) {
        CP_WAIT2();
        __syncthreads();
        const uint32_t st = sb + (t % NSTAGE) * STAGEB;

        // Refill tile t+3 into slot (t+3)%4 (readers done at iter t-1)
        if (t + 3 < KT) {
            const uint32_t st2 = sb + ((t + 3) % NSTAGE) * STAGEB;
            const int kc = (t + 3) * 16;
            CP16(st2 + sdst,          gsrcA + kc);
            CP16(st2 + PLANEB + sdst, gsrcB + kc);
        }
        CP_COMMIT();

        unsigned bf[4][2];
#pragma unroll
        for (int j = 0; j < 2; j++) {
            unsigned r0, r1, r2, r3;
            LDSM4(r0, r1, r2, r3, st + PLANEB + bbase + j * (16 * ROWB));
            bf[2 * j][0] = r0; bf[2 * j + 1][0] = r1;
            bf[2 * j][1] = r2; bf[2 * j + 1][1] = r3;
        }
#pragma unroll
        for (int mt = 0; mt < 4; mt++) {
            unsigned af[4];
            LDSM4(af[0], af[1], af[2], af[3], st + abase + mt * (16 * ROWB));
#pragma unroll
            for (int nt = 0; nt < 4; nt++)
                mma_fp(acc[mt][nt], af, bf[nt]);
        }
    }

    const int g = lane >> 2, tig = lane & 3;
    if (!FUSED) {
#pragma unroll
        for (int mt = 0; mt < 4; mt++)
#pragma unroll
            for (int nt = 0; nt < 4; nt++) {
                int row = m0 + wm + mt * 16 + g;
                int cc = col0 + wn + nt * 8 + 2 * tig;
                *(float2*)(out + (size_t)row * DM + cc) =
                    make_float2(acc[mt][nt][0], acc[mt][nt][1]);
                *(float2*)(out + (size_t)(row + 8) * DM + cc) =
                    make_float2(acc[mt][nt][2], acc[mt][nt][3]);
            }
    } else {
        const int grp = nb >> 3;   // 0=q, 1=k, 2=v (uniform per block)
#pragma unroll
        for (int mt = 0; mt < 4; mt++)
#pragma unroll
            for (int nt = 0; nt < 4; nt++) {
                int row = m0 + wm + mt * 16 + g;
                int cc = col0 + wn + nt * 8 + 2 * tig;
                if (grp == 0) {
                    __half2 h0 = __floats2half2_rn(acc[mt][nt][0] * QSCALE,
                                                   acc[mt][nt][1] * QSCALE);
                    __half2 h1 = __floats2half2_rn(acc[mt][nt][2] * QSCALE,
                                                   acc[mt][nt][3] * QSCALE);
                    *(unsigned*)(g_qh + (size_t)row * DM + cc) = *(unsigned*)&h0;
                    *(unsigned*)(g_qh + (size_t)(row + 8) * DM + cc) = *(unsigned*)&h1;
                } else if (grp == 1) {
                    __half2 h0 = __floats2half2_rn(acc[mt][nt][0], acc[mt][nt][1]);
                    __half2 h1 = __floats2half2_rn(acc[mt][nt][2], acc[mt][nt][3]);
                    *(unsigned*)(g_kh + (size_t)row * DM + cc) = *(unsigned*)&h0;
                    *(unsigned*)(g_kh + (size_t)(row + 8) * DM + cc) = *(unsigned*)&h1;
                } else {
                    float a0 = acc[mt][nt][0], a1 = acc[mt][nt][1];
                    float a2 = acc[mt][nt][2], a3 = acc[mt][nt][3];
                    float b0 = __shfl_down_sync(0xffffffffu, a0, 4);
                    float b1 = __shfl_down_sync(0xffffffffu, a1, 4);
                    float b2 = __shfl_down_sync(0xffffffffu, a2, 4);
                    float b3 = __shfl_down_sync(0xffffffffu, a3, 4);
                    if (!(g & 1)) {
                        int prow = row >> 1;
                        __half2 p0 = __floats2half2_rn(a0, b0);
                        __half2 p1 = __floats2half2_rn(a1, b1);
                        *(uint2*)(g_vp + (size_t)prow * DM + cc) =
                            make_uint2(*(unsigned*)&p0, *(unsigned*)&p1);
                        __half2 p2 = __floats2half2_rn(a2, b2);
                        __half2 p3 = __floats2half2_rn(a3, b3);
                        *(uint2*)(g_vp + (size_t)(prow + 4) * DM + cc) =
                            make_uint2(*(unsigned*)&p2, *(unsigned*)&p3);
                    }
                }
            }
    }
}

// ---------------------------------------------------------------------------
// Warp-tiled flash attention (unchanged from the 196.5us run).
// ---------------------------------------------------------------------------
__global__ void __launch_bounds__(128, 4) attn_kernel(int qblk_off)
{
    __shared__ unsigned Qh[64][36];
    __shared__ unsigned Kh[64][36];
    __shared__ unsigned Vs[32][72];
    __shared__ unsigned Ps[64][36];

    const int h = blockIdx.y, t0 = (blockIdx.x + qblk_off) * 64;
    const int tid = threadIdx.x;
    const int lane = tid & 31, warp = tid >> 5;
    const int g = lane >> 2, tig = lane & 3;
    const int wq = t0 + warp * 16;
    const int rA = warp * 16 + g;

#pragma unroll
    for (int u = 0; u < 4; u++) {
        int idx = tid + u * 128;
        int r = idx >> 3, c = idx & 7;
        *(uint4*)&Qh[r][c * 4] =
            *(const uint4*)(g_qh + (size_t)(t0 + r) * DM + h * DH + c * 8);
    }

    float o[8][4];
#pragma unroll
    for (int nt = 0; nt < 8; nt++)
#pragma unroll
        for (int e = 0; e < 4; e++) o[nt][e] = 0.0f;
    float m0 = -1e30f, m1 = -1e30f, l0 = 0.0f, l1 = 0.0f;

    const int jlo = max(0, t0 - WIN);

    for (int jc = t0; jc >= jlo; jc -= 64) {
        __syncthreads();
#pragma unroll
        for (int u = 0; u < 4; u++) {
            int idx = tid + u * 128;
            int r = idx >> 3, c = idx & 7;
            *(uint4*)&Kh[r][c * 4] =
                *(const uint4*)(g_kh + (size_t)(jc + r) * DM + h * DH + c * 8);
        }
#pragma unroll
        for (int u = 0; u < 4; u++) {
            int idx = tid + u * 128;
            int r = idx >> 4, c = idx & 15;
            *(uint4*)&Vs[r][c * 4] =
                *(const uint4*)(g_vp + (size_t)((jc >> 1) + r) * DM + h * DH + c * 4);
        }
        __syncthreads();

        const bool is_first = (jc == t0);
        const bool is_last  = (jc == t0 - WIN);
        const int nt0 = is_last ? 2 * warp : 0;
        const int ks0 = is_last ? warp : 0;

        float s[8][4];
#pragma unroll
        for (int nt = 0; nt < 8; nt++)
#pragma unroll
            for (int e = 0; e < 4; e++) s[nt][e] = 0.0f;
#pragma unroll
        for (int ks = 0; ks < 4; ks++) {
            unsigned qf[4];
            qf[0] = Qh[rA][ks * 8 + tig];     qf[1] = Qh[rA + 8][ks * 8 + tig];
            qf[2] = Qh[rA][ks * 8 + tig + 4]; qf[3] = Qh[rA + 8][ks * 8 + tig + 4];
#pragma unroll
            for (int nt = 0; nt < 8; nt++) {
                if (nt >= nt0) {
                    unsigned bf[2];
                    bf[0] = Kh[nt * 8 + g][ks * 8 + tig];
                    bf[1] = Kh[nt * 8 + g][ks * 8 + tig + 4];
                    mma_fp(s[nt], qf, bf);
                }
            }
        }

        const int r0 = wq + g, r1 = r0 + 8;
        if (is_first || is_last) {
#pragma unroll
            for (int nt = 0; nt < 8; nt++) {
#pragma unroll
                for (int e = 0; e < 2; e++) {
                    int j = jc + nt * 8 + 2 * tig + e;
                    if (j > r0 || j + WIN < r0) s[nt][e] = -1e30f;
                    if (j > r1 || j + WIN < r1) s[nt][2 + e] = -1e30f;
                }
            }
        }

        float mx0 = -1e30f, mx1 = -1e30f;
#pragma unroll
        for (int nt = 0; nt < 8; nt++) {
            mx0 = fmaxf(mx0, fmaxf(s[nt][0], s[nt][1]));
            mx1 = fmaxf(mx1, fmaxf(s[nt][2], s[nt][3]));
        }
        mx0 = fmaxf(mx0, __shfl_xor_sync(0xffffffffu, mx0, 1));
        mx0 = fmaxf(mx0, __shfl_xor_sync(0xffffffffu, mx0, 2));
        mx1 = fmaxf(mx1, __shfl_xor_sync(0xffffffffu, mx1, 1));
        mx1 = fmaxf(mx1, __shfl_xor_sync(0xffffffffu, mx1, 2));
        float mn0 = fmaxf(m0, mx0), mn1 = fmaxf(m1, mx1);
        float c0 = ex2(m0 - mn0), c1 = ex2(m1 - mn1);
        m0 = mn0; m1 = mn1;
        l0 *= c0; l1 *= c1;
#pragma unroll
        for (int nt = 0; nt < 8; nt++) {
            o[nt][0] *= c0; o[nt][1] *= c0;
            o[nt][2] *= c1; o[nt][3] *= c1;
        }
        float ls0 = 0.0f, ls1 = 0.0f;
#pragma unroll
        for (int nt = 0; nt < 8; nt++) {
            float p00 = ex2(s[nt][0] - mn0), p01 = ex2(s[nt][1] - mn0);
            float p10 = ex2(s[nt][2] - mn1), p11 = ex2(s[nt][3] - mn1);
            ls0 += p00 + p01; ls1 += p10 + p11;
            __half2 w0 = __floats2half2_rn(p00, p01);
            __half2 w1 = __floats2half2_rn(p10, p11);
            Ps[rA][nt * 4 + tig] = *(unsigned*)&w0;
            Ps[rA + 8][nt * 4 + tig] = *(unsigned*)&w1;
        }
        ls0 += __shfl_xor_sync(0xffffffffu, ls0, 1);
        ls0 += __shfl_xor_sync(0xffffffffu, ls0, 2);
        ls1 += __shfl_xor_sync(0xffffffffu, ls1, 1);
        ls1 += __shfl_xor_sync(0xffffffffu, ls1, 2);
        l0 += ls0; l1 += ls1;
        __syncwarp();

#pragma unroll
        for (int ks2 = 0; ks2 < 4; ks2++) {
            if (ks2 >= ks0) {
                unsigned pa[4];
                pa[0] = Ps[rA][ks2 * 8 + tig];
                pa[1] = Ps[rA + 8][ks2 * 8 + tig];
                pa[2] = Ps[rA][ks2 * 8 + tig + 4];
                pa[3] = Ps[rA + 8][ks2 * 8 + tig + 4];
#pragma unroll
                for (int nt = 0; nt < 8; nt++) {
                    unsigned vb[2];
                    vb[0] = Vs[ks2 * 8 + tig][nt * 8 + g];
                    vb[1] = Vs[ks2 * 8 + tig + 4][nt * 8 + g];
                    mma_fp(o[nt], pa, vb);
                }
            }
        }
    }

    const float inv0 = 1.0f / l0, inv1 = 1.0f / l1;
#pragma unroll
    for (int nt = 0; nt < 8; nt++) {
        int col = h * DH + nt * 8 + 2 * tig;
        __half2 a = __floats2half2_rn(o[nt][0] * inv0, o[nt][1] * inv0);
        __half2 b = __floats2half2_rn(o[nt][2] * inv1, o[nt][3] * inv1);
        *(unsigned*)(g_ao + (size_t)(wq + g) * DM + col) = *(unsigned*)&a;
        *(unsigned*)(g_ao + (size_t)(wq + g + 8) * DM + col) = *(unsigned*)&b;
    }
}

// ---------------------------------------------------------------------------
// Launch: R12 schedule with ONE change — O-B runs on s2 right after attnB
// (instead of joining to legacy and running both O-halves serially).
//   legacy: conv -> QKV-A -> attnA -> O-A -> (wait evB) done
//   s2 (low prio): QKV-B -> attnB -> O-B
// ---------------------------------------------------------------------------
extern "C" void kernel_launch(void* const* d_in, const int* in_sizes, int n_in,
                              void* d_out, int out_size)
{
    const float* x  = (const float*)d_in[0];
    const float* Wq = (const float*)d_in[1];
    const float* Wk = (const float*)d_in[2];
    const float* Wv = (const float*)d_in[3];
    const float* Wo = (const float*)d_in[4];
    float* out = (float*)d_out;

    __half *xh, *ao, *wt;
    cudaGetSymbolAddress((void**)&xh, g_xh);
    cudaGetSymbolAddress((void**)&ao, g_ao);
    cudaGetSymbolAddress((void**)&wt, g_wt);

    cudaFuncSetAttribute(gemm_fp16<true>,  cudaFuncAttributeMaxDynamicSharedMemorySize, GSMEM);
    cudaFuncSetAttribute(gemm_fp16<false>, cudaFuncAttributeMaxDynamicSharedMemorySize, GSMEM);

    int prLo = 0, prHi = 0;
    cudaDeviceGetStreamPriorityRange(&prLo, &prHi);   // prLo = least urgent
    cudaStream_t s2;
    cudaStreamCreateWithPriority(&s2, cudaStreamNonBlocking, prLo);
    cudaEvent_t evConv, evA, evB;
    cudaEventCreateWithFlags(&evConv, cudaEventDisableTiming);
    cudaEventCreateWithFlags(&evA,    cudaEventDisableTiming);
    cudaEventCreateWithFlags(&evB,    cudaEventDisableTiming);

    // One-time conversions (legacy stream)
    tsplit4h<<<dim3(DM / 32, DM / 32, 4), dim3(32, 8)>>>(Wq, Wk, Wv, Wo, wt);
    tohalf<<<SEQ * DM / 1024, 256>>>(x, xh);
    cudaEventRecord(evConv, 0);
    cudaStreamWaitEvent(s2, evConv, 0);

    // QKV GEMM, row-halved: A on legacy (high prio), B on s2 (low prio)
    gemm_fp16<true><<<dim3(24, SEQ / 256), 256, GSMEM, 0>>>(xh, wt, nullptr, 0);
    gemm_fp16<true><<<dim3(24, SEQ / 256), 256, GSMEM, s2>>>(xh, wt, nullptr, SEQ / 2);
    cudaEventRecord(evA, 0);

    // Attention halves
    attn_kernel<<<dim3(32, NH), 128, 0, 0>>>(0);          // rows 0..2047 only
    cudaStreamWaitEvent(s2, evA, 0);
    attn_kernel<<<dim3(32, NH), 128, 0, s2>>>(32);        // needs both halves

    // O-projection halves: O-A on legacy after attnA, O-B on s2 after attnB
    gemm_fp16<false><<<dim3(8, SEQ / 256), 256, GSMEM, 0>>>(
        ao, wt + 3 * (size_t)DM * DM, out, 0);
    gemm_fp16<false><<<dim3(8, SEQ / 256), 256, GSMEM, s2>>>(
        ao, wt + 3 * (size_t)DM * DM, out, SEQ / 2);
    cudaEventRecord(evB, s2);
    cudaStreamWaitEvent(0, evB, 0);                        // join fork at the end
}

// round 16
// speedup vs baseline: 1.1419x; 1.0122x over previous
#include <cuda_runtime.h>
#include <cuda_bf16.h>
#include <cuda_fp16.h>
#include <cstdint>

#define SEQ 4096
#define DM  1024
#define NH  16
#define DH  64
#define WIN 256

// ---------------------------------------------------------------------------
// Scratch (allocation-free rule)
// ---------------------------------------------------------------------------
__device__ __half    g_qh[SEQ * DM];          // q (pre-scaled 0.125*log2e), fp16
__device__ __half    g_kh[SEQ * DM];          // k, fp16
__device__ unsigned  g_vp[(SEQ / 2) * DM];    // v, fp16 k-pair-packed
__device__ __half    g_xh[SEQ * DM];          // x as fp16
__device__ __half    g_ao[SEQ * DM];          // attention output as fp16
__device__ __half    g_wt[4][DM * DM];        // W^T as fp16 (q,k,v,o)

// ---------------------------------------------------------------------------
// Helpers
// ---------------------------------------------------------------------------
__device__ __forceinline__ uint32_t smem_u32(const void* p) {
    uint32_t a;
    asm("{ .reg .u64 t; cvta.to.shared.u64 t, %1; cvt.u32.u64 %0, t; }" : "=r"(a) : "l"(p));
    return a;
}
__device__ __forceinline__ float ex2(float x) {
    float r; asm("ex2.approx.ftz.f32 %0, %1;" : "=f"(r) : "f"(x)); return r;
}
// fp16 MMA m16n8k16, fp32 accum
__device__ __forceinline__ void mma_fp(float* c, const unsigned* a, const unsigned* b) {
    asm volatile("mma.sync.aligned.m16n8k16.row.col.f32.f16.f16.f32 "
        "{%0,%1,%2,%3},{%4,%5,%6,%7},{%8,%9},{%0,%1,%2,%3};"
        : "+f"(c[0]), "+f"(c[1]), "+f"(c[2]), "+f"(c[3])
        : "r"(a[0]), "r"(a[1]), "r"(a[2]), "r"(a[3]), "r"(b[0]), "r"(b[1]));
}
#define CP16(dst, src) \
    asm volatile("cp.async.cg.shared.global [%0], [%1], 16;" :: "r"(dst), "l"(src))
#define CP_COMMIT() asm volatile("cp.async.commit_group;" ::: "memory")
#define CP_WAIT2()  asm volatile("cp.async.wait_group 2;" ::: "memory")
#define LDSM4(r0, r1, r2, r3, a) \
    asm volatile("ldmatrix.sync.aligned.m8n8.x4.shared.b16 {%0,%1,%2,%3}, [%4];" \
        : "=r"(r0), "=r"(r1), "=r"(r2), "=r"(r3) : "r"(a))

// q scale: 0.125 (1/sqrt(64)) * log2(e), folded so softmax can use exp2
#define QSCALE 0.180336880f

// ---------------------------------------------------------------------------
// Fused conversion kernel (single launch):
//   blocks [0, 4096):    W^T transpose-split tiles (exact tsplit4h math)
//   blocks [4096, 8192): x -> fp16 copy (exact tohalf math)
// Block = 256 threads, laid out (32, 8) for the transpose part.
// ---------------------------------------------------------------------------
__global__ void convert_all(const float* __restrict__ x,
                            const float* __restrict__ W0, const float* __restrict__ W1,
                            const float* __restrict__ W2, const float* __restrict__ W3,
                            __half* __restrict__ xh, __half* __restrict__ T) {
    const int bid = blockIdx.x;
    const int tx = threadIdx.x, ty = threadIdx.y;
    const int tid = ty * 32 + tx;

    if (bid < 4096) {
        // --- W^T transpose-split tile ---
        __shared__ float tile[32][33];
        const int z = bid >> 10;               // 0..3
        const int rest = bid & 1023;
        const int n0 = (rest & 31) * 32;       // == old blockIdx.x * 32
        const int k0 = (rest >> 5) * 32;       // == old blockIdx.y * 32
        const float* W = z == 0 ? W0 : (z == 1 ? W1 : (z == 2 ? W2 : W3));
        __half* t_out = T + (size_t)z * DM * DM;
#pragma unroll
        for (int j = 0; j < 32; j += 8)
            tile[ty + j][tx] = W[(size_t)(k0 + ty + j) * DM + n0 + tx];
        __syncthreads();
#pragma unroll
        for (int j = 0; j < 32; j += 8)
            t_out[(size_t)(n0 + ty + j) * DM + k0 + tx] = __float2half(tile[tx][ty + j]);
    } else {
        // --- x -> fp16 ---
        const int i = ((bid - 4096) * 256 + tid) * 4;
        float4 v = *(const float4*)(x + i);
        __half2 a = __floats2half2_rn(v.x, v.y);
        __half2 b = __floats2half2_rn(v.z, v.w);
        *(uint2*)(xh + i) = make_uint2(*(unsigned*)&a, *(unsigned*)&b);
    }
}

// ---------------------------------------------------------------------------
// Pipelined 1-pass fp16 HMMA GEMM — unchanged from the 188.7us run:
// 256 thr (8 warps 2x4), tile 128x128, BK=16, 4-slot / 3-deep cp.async ring,
// single __syncthreads per iteration. FUSED epilogue writes q/k/v attention
// scratch; else fp32 out. m_base selects the row-half.
// ---------------------------------------------------------------------------
#define ROWB    48
#define PLANEB  (128 * ROWB)        // 6144
#define STAGEB  (2 * PLANEB)        // 12288
#define NSTAGE  4
#define GSMEM   (NSTAGE * STAGEB)   // 49152

template <bool FUSED>
__global__ void __launch_bounds__(256, 2) gemm_fp16(
    const __half* __restrict__ A, const __half* __restrict__ BT,
    float* __restrict__ out, int m_base)
{
    extern __shared__ char dynsmem[];
    const uint32_t sb = smem_u32(dynsmem);
    const int tid = threadIdx.x, lane = tid & 31, warp = tid >> 5;
    const int m0 = m_base + blockIdx.y * 128;
    const int nb = blockIdx.x;
    const int nbase = nb * 128;
    const int col0 = (nb & 7) * 128;

    const int r = tid >> 1, hf = tid & 1;
    const __half* gsrcA = A  + (size_t)(m0 + r) * DM + hf * 8;
    const __half* gsrcB = BT + (size_t)(nbase + r) * DM + hf * 8;
    const uint32_t sdst = r * ROWB + hf * 16;

    const int wm = (warp >> 2) * 64, wn = (warp & 3) * 32;
    const int lrow = lane & 15, lcol = lane & 16;
    const uint32_t abase = (wm + lrow) * ROWB + lcol;
    const uint32_t bbase = (wn + lrow) * ROWB + lcol;

    float acc[4][4][4];
#pragma unroll
    for (int a = 0; a < 4; a++)
#pragma unroll
        for (int b = 0; b < 4; b++)
#pragma unroll
            for (int c = 0; c < 4; c++) acc[a][b][c] = 0.0f;

    // Prologue: tiles 0..2 into slots 0..2 (3-deep)
#pragma unroll
    for (int t = 0; t < 3; t++) {
        const uint32_t st = sb + t * STAGEB;
        const int kc = t * 16;
        CP16(st + sdst,          gsrcA + kc);
        CP16(st + PLANEB + sdst, gsrcB + kc);
        CP_COMMIT();
    }

    const int KT = DM / 16;  // 64
    for (int t = 0; t < KT; t++) {
        CP_WAIT2();
        __syncthreads();
        const uint32_t st = sb + (t % NSTAGE) * STAGEB;

        // Refill tile t+3 into slot (t+3)%4 (readers done at iter t-1)
        if (t + 3 < KT) {
            const uint32_t st2 = sb + ((t + 3) % NSTAGE) * STAGEB;
            const int kc = (t + 3) * 16;
            CP16(st2 + sdst,          gsrcA + kc);
            CP16(st2 + PLANEB + sdst, gsrcB + kc);
        }
        CP_COMMIT();

        unsigned bf[4][2];
#pragma unroll
        for (int j = 0; j < 2; j++) {
            unsigned r0, r1, r2, r3;
            LDSM4(r0, r1, r2, r3, st + PLANEB + bbase + j * (16 * ROWB));
            bf[2 * j][0] = r0; bf[2 * j + 1][0] = r1;
            bf[2 * j][1] = r2; bf[2 * j + 1][1] = r3;
        }
#pragma unroll
        for (int mt = 0; mt < 4; mt++) {
            unsigned af[4];
            LDSM4(af[0], af[1], af[2], af[3], st + abase + mt * (16 * ROWB));
#pragma unroll
            for (int nt = 0; nt < 4; nt++)
                mma_fp(acc[mt][nt], af, bf[nt]);
        }
    }

    const int g = lane >> 2, tig = lane & 3;
    if (!FUSED) {
#pragma unroll
        for (int mt = 0; mt < 4; mt++)
#pragma unroll
            for (int nt = 0; nt < 4; nt++) {
                int row = m0 + wm + mt * 16 + g;
                int cc = col0 + wn + nt * 8 + 2 * tig;
                *(float2*)(out + (size_t)row * DM + cc) =
                    make_float2(acc[mt][nt][0], acc[mt][nt][1]);
                *(float2*)(out + (size_t)(row + 8) * DM + cc) =
                    make_float2(acc[mt][nt][2], acc[mt][nt][3]);
            }
    } else {
        const int grp = nb >> 3;   // 0=q, 1=k, 2=v (uniform per block)
#pragma unroll
        for (int mt = 0; mt < 4; mt++)
#pragma unroll
            for (int nt = 0; nt < 4; nt++) {
                int row = m0 + wm + mt * 16 + g;
                int cc = col0 + wn + nt * 8 + 2 * tig;
                if (grp == 0) {
                    __half2 h0 = __floats2half2_rn(acc[mt][nt][0] * QSCALE,
                                                   acc[mt][nt][1] * QSCALE);
                    __half2 h1 = __floats2half2_rn(acc[mt][nt][2] * QSCALE,
                                                   acc[mt][nt][3] * QSCALE);
                    *(unsigned*)(g_qh + (size_t)row * DM + cc) = *(unsigned*)&h0;
                    *(unsigned*)(g_qh + (size_t)(row + 8) * DM + cc) = *(unsigned*)&h1;
                } else if (grp == 1) {
                    __half2 h0 = __floats2half2_rn(acc[mt][nt][0], acc[mt][nt][1]);
                    __half2 h1 = __floats2half2_rn(acc[mt][nt][2], acc[mt][nt][3]);
                    *(unsigned*)(g_kh + (size_t)row * DM + cc) = *(unsigned*)&h0;
                    *(unsigned*)(g_kh + (size_t)(row + 8) * DM + cc) = *(unsigned*)&h1;
                } else {
                    float a0 = acc[mt][nt][0], a1 = acc[mt][nt][1];
                    float a2 = acc[mt][nt][2], a3 = acc[mt][nt][3];
                    float b0 = __shfl_down_sync(0xffffffffu, a0, 4);
                    float b1 = __shfl_down_sync(0xffffffffu, a1, 4);
                    float b2 = __shfl_down_sync(0xffffffffu, a2, 4);
                    float b3 = __shfl_down_sync(0xffffffffu, a3, 4);
                    if (!(g & 1)) {
                        int prow = row >> 1;
                        __half2 p0 = __floats2half2_rn(a0, b0);
                        __half2 p1 = __floats2half2_rn(a1, b1);
                        *(uint2*)(g_vp + (size_t)prow * DM + cc) =
                            make_uint2(*(unsigned*)&p0, *(unsigned*)&p1);
                        __half2 p2 = __floats2half2_rn(a2, b2);
                        __half2 p3 = __floats2half2_rn(a3, b3);
                        *(uint2*)(g_vp + (size_t)(prow + 4) * DM + cc) =
                            make_uint2(*(unsigned*)&p2, *(unsigned*)&p3);
                    }
                }
            }
    }
}

// ---------------------------------------------------------------------------
// Warp-tiled flash attention (unchanged from the 188.7us run).
// ---------------------------------------------------------------------------
__global__ void __launch_bounds__(128, 4) attn_kernel(int qblk_off)
{
    __shared__ unsigned Qh[64][36];
    __shared__ unsigned Kh[64][36];
    __shared__ unsigned Vs[32][72];
    __shared__ unsigned Ps[64][36];

    const int h = blockIdx.y, t0 = (blockIdx.x + qblk_off) * 64;
    const int tid = threadIdx.x;
    const int lane = tid & 31, warp = tid >> 5;
    const int g = lane >> 2, tig = lane & 3;
    const int wq = t0 + warp * 16;
    const int rA = warp * 16 + g;

#pragma unroll
    for (int u = 0; u < 4; u++) {
        int idx = tid + u * 128;
        int r = idx >> 3, c = idx & 7;
        *(uint4*)&Qh[r][c * 4] =
            *(const uint4*)(g_qh + (size_t)(t0 + r) * DM + h * DH + c * 8);
    }

    float o[8][4];
#pragma unroll
    for (int nt = 0; nt < 8; nt++)
#pragma unroll
        for (int e = 0; e < 4; e++) o[nt][e] = 0.0f;
    float m0 = -1e30f, m1 = -1e30f, l0 = 0.0f, l1 = 0.0f;

    const int jlo = max(0, t0 - WIN);

    for (int jc = t0; jc >= jlo; jc -= 64) {
        __syncthreads();
#pragma unroll
        for (int u = 0; u < 4; u++) {
            int idx = tid + u * 128;
            int r = idx >> 3, c = idx & 7;
            *(uint4*)&Kh[r][c * 4] =
                *(const uint4*)(g_kh + (size_t)(jc + r) * DM + h * DH + c * 8);
        }
#pragma unroll
        for (int u = 0; u < 4; u++) {
            int idx = tid + u * 128;
            int r = idx >> 4, c = idx & 15;
            *(uint4*)&Vs[r][c * 4] =
                *(const uint4*)(g_vp + (size_t)((jc >> 1) + r) * DM + h * DH + c * 4);
        }
        __syncthreads();

        const bool is_first = (jc == t0);
        const bool is_last  = (jc == t0 - WIN);
        const int nt0 = is_last ? 2 * warp : 0;
        const int ks0 = is_last ? warp : 0;

        float s[8][4];
#pragma unroll
        for (int nt = 0; nt < 8; nt++)
#pragma unroll
            for (int e = 0; e < 4; e++) s[nt][e] = 0.0f;
#pragma unroll
        for (int ks = 0; ks < 4; ks++) {
            unsigned qf[4];
            qf[0] = Qh[rA][ks * 8 + tig];     qf[1] = Qh[rA + 8][ks * 8 + tig];
            qf[2] = Qh[rA][ks * 8 + tig + 4]; qf[3] = Qh[rA + 8][ks * 8 + tig + 4];
#pragma unroll
            for (int nt = 0; nt < 8; nt++) {
                if (nt >= nt0) {
                    unsigned bf[2];
                    bf[0] = Kh[nt * 8 + g][ks * 8 + tig];
                    bf[1] = Kh[nt * 8 + g][ks * 8 + tig + 4];
                    mma_fp(s[nt], qf, bf);
                }
            }
        }

        const int r0 = wq + g, r1 = r0 + 8;
        if (is_first || is_last) {
#pragma unroll
            for (int nt = 0; nt < 8; nt++) {
#pragma unroll
                for (int e = 0; e < 2; e++) {
                    int j = jc + nt * 8 + 2 * tig + e;
                    if (j > r0 || j + WIN < r0) s[nt][e] = -1e30f;
                    if (j > r1 || j + WIN < r1) s[nt][2 + e] = -1e30f;
                }
            }
        }

        float mx0 = -1e30f, mx1 = -1e30f;
#pragma unroll
        for (int nt = 0; nt < 8; nt++) {
            mx0 = fmaxf(mx0, fmaxf(s[nt][0], s[nt][1]));
            mx1 = fmaxf(mx1, fmaxf(s[nt][2], s[nt][3]));
        }
        mx0 = fmaxf(mx0, __shfl_xor_sync(0xffffffffu, mx0, 1));
        mx0 = fmaxf(mx0, __shfl_xor_sync(0xffffffffu, mx0, 2));
        mx1 = fmaxf(mx1, __shfl_xor_sync(0xffffffffu, mx1, 1));
        mx1 = fmaxf(mx1, __shfl_xor_sync(0xffffffffu, mx1, 2));
        float mn0 = fmaxf(m0, mx0), mn1 = fmaxf(m1, mx1);
        float c0 = ex2(m0 - mn0), c1 = ex2(m1 - mn1);
        m0 = mn0; m1 = mn1;
        l0 *= c0; l1 *= c1;
#pragma unroll
        for (int nt = 0; nt < 8; nt++) {
            o[nt][0] *= c0; o[nt][1] *= c0;
            o[nt][2] *= c1; o[nt][3] *= c1;
        }
        float ls0 = 0.0f, ls1 = 0.0f;
#pragma unroll
        for (int nt = 0; nt < 8; nt++) {
            float p00 = ex2(s[nt][0] - mn0), p01 = ex2(s[nt][1] - mn0);
            float p10 = ex2(s[nt][2] - mn1), p11 = ex2(s[nt][3] - mn1);
            ls0 += p00 + p01; ls1 += p10 + p11;
            __half2 w0 = __floats2half2_rn(p00, p01);
            __half2 w1 = __floats2half2_rn(p10, p11);
            Ps[rA][nt * 4 + tig] = *(unsigned*)&w0;
            Ps[rA + 8][nt * 4 + tig] = *(unsigned*)&w1;
        }
        ls0 += __shfl_xor_sync(0xffffffffu, ls0, 1);
        ls0 += __shfl_xor_sync(0xffffffffu, ls0, 2);
        ls1 += __shfl_xor_sync(0xffffffffu, ls1, 1);
        ls1 += __shfl_xor_sync(0xffffffffu, ls1, 2);
        l0 += ls0; l1 += ls1;
        __syncwarp();

#pragma unroll
        for (int ks2 = 0; ks2 < 4; ks2++) {
            if (ks2 >= ks0) {
                unsigned pa[4];
                pa[0] = Ps[rA][ks2 * 8 + tig];
                pa[1] = Ps[rA + 8][ks2 * 8 + tig];
                pa[2] = Ps[rA][ks2 * 8 + tig + 4];
                pa[3] = Ps[rA + 8][ks2 * 8 + tig + 4];
#pragma unroll
                for (int nt = 0; nt < 8; nt++) {
                    unsigned vb[2];
                    vb[0] = Vs[ks2 * 8 + tig][nt * 8 + g];
                    vb[1] = Vs[ks2 * 8 + tig + 4][nt * 8 + g];
                    mma_fp(o[nt], pa, vb);
                }
            }
        }
    }

    const float inv0 = 1.0f / l0, inv1 = 1.0f / l1;
#pragma unroll
    for (int nt = 0; nt < 8; nt++) {
        int col = h * DH + nt * 8 + 2 * tig;
        __half2 a = __floats2half2_rn(o[nt][0] * inv0, o[nt][1] * inv0);
        __half2 b = __floats2half2_rn(o[nt][2] * inv1, o[nt][3] * inv1);
        *(unsigned*)(g_ao + (size_t)(wq + g) * DM + col) = *(unsigned*)&a;
        *(unsigned*)(g_ao + (size_t)(wq + g + 8) * DM + col) = *(unsigned*)&b;
    }
}

// ---------------------------------------------------------------------------
// Launch: R14 schedule (the 188.7us winner) with the two conversion kernels
// fused into ONE launch.
//   legacy: convert_all -> QKV-A -> attnA -> O-A -> (wait evB) done
//   s2 (low prio): QKV-B -> attnB -> O-B
// ---------------------------------------------------------------------------
extern "C" void kernel_launch(void* const* d_in, const int* in_sizes, int n_in,
                              void* d_out, int out_size)
{
    const float* x  = (const float*)d_in[0];
    const float* Wq = (const float*)d_in[1];
    const float* Wk = (const float*)d_in[2];
    const float* Wv = (const float*)d_in[3];
    const float* Wo = (const float*)d_in[4];
    float* out = (float*)d_out;

    __half *xh, *ao, *wt;
    cudaGetSymbolAddress((void**)&xh, g_xh);
    cudaGetSymbolAddress((void**)&ao, g_ao);
    cudaGetSymbolAddress((void**)&wt, g_wt);

    cudaFuncSetAttribute(gemm_fp16<true>,  cudaFuncAttributeMaxDynamicSharedMemorySize, GSMEM);
    cudaFuncSetAttribute(gemm_fp16<false>, cudaFuncAttributeMaxDynamicSharedMemorySize, GSMEM);

    int prLo = 0, prHi = 0;
    cudaDeviceGetStreamPriorityRange(&prLo, &prHi);   // prLo = least urgent
    cudaStream_t s2;
    cudaStreamCreateWithPriority(&s2, cudaStreamNonBlocking, prLo);
    cudaEvent_t evConv, evA, evB;
    cudaEventCreateWithFlags(&evConv, cudaEventDisableTiming);
    cudaEventCreateWithFlags(&evA,    cudaEventDisableTiming);
    cudaEventCreateWithFlags(&evB,    cudaEventDisableTiming);

    // Fused one-shot conversion (legacy stream)
    convert_all<<<8192, dim3(32, 8)>>>(x, Wq, Wk, Wv, Wo, xh, wt);
    cudaEventRecord(evConv, 0);
    cudaStreamWaitEvent(s2, evConv, 0);

    // QKV GEMM, row-halved: A on legacy (high prio), B on s2 (low prio)
    gemm_fp16<true><<<dim3(24, SEQ / 256), 256, GSMEM, 0>>>(xh, wt, nullptr, 0);
    gemm_fp16<true><<<dim3(24, SEQ / 256), 256, GSMEM, s2>>>(xh, wt, nullptr, SEQ / 2);
    cudaEventRecord(evA, 0);

    // Attention halves
    attn_kernel<<<dim3(32, NH), 128, 0, 0>>>(0);          // rows 0..2047 only
    cudaStreamWaitEvent(s2, evA, 0);
    attn_kernel<<<dim3(32, NH), 128, 0, s2>>>(32);        // needs both halves

    // O-projection halves: O-A on legacy after attnA, O-B on s2 after attnB
    gemm_fp16<false><<<dim3(8, SEQ / 256), 256, GSMEM, 0>>>(
        ao, wt + 3 * (size_t)DM * DM, out, 0);
    gemm_fp16<false><<<dim3(8, SEQ / 256), 256, GSMEM, s2>>>(
        ao, wt + 3 * (size_t)DM * DM, out, SEQ / 2);
    cudaEventRecord(evB, s2);
    cudaStreamWaitEvent(0, evB, 0);                        // join fork at the end
}